// round 15
// baseline (speedup 1.0000x reference)
#include <cuda_runtime.h>
#include <cuda_fp16.h>
#include <cstdint>

#define B_      8
#define AT_     96
#define NBR_    512
#define NANG_   125
#define NF_     128
#define NB_     128
#define ATOMS_  (B_*AT_)      // 768
#define CHUNK_  64
#define NCHUNK_ (NBR_/CHUNK_) // 8
#define PH_     68            // half2-word pitch (%32==4 -> conflict-free)

// smem layout (u32 units): 6 tile buffers (T0,T1,H0,H1,W0,W1) + extras
#define SM_T0   0
#define SM_T1   4352
#define SM_H0   8704
#define SM_H1   13056
#define SM_W0   17408
#define SM_W1   21760
#define SM_EX   26112
// EX floats: b1s[128] b2s[128] js4[256] ks4[256] ms4[256] = 1024
#define SMEM_U32   (SM_EX + 1024)
#define SMEM_BYTES (SMEM_U32*4)   // 108,544 B -> 2 CTAs/SM (217KB)

__device__ __align__(16) uint32_t g_y16[ATOMS_ * 64];   // y as half2 words
__device__ __align__(16) uint32_t g_W1p[2048*4];
__device__ __align__(16) uint32_t g_W2p[2048*4];

__device__ __forceinline__ float sspf(float x) {
    return fmaxf(x, 0.f) + __logf(1.f + __expf(-fabsf(x))) - 0.6931471805599453f;
}
__device__ __forceinline__ uint32_t packh2(float lo, float hi) {
    __half2 h = __halves2half2(__float2half_rn(lo), __float2half_rn(hi));
    return *reinterpret_cast<uint32_t*>(&h);
}
__device__ __forceinline__ float2 h2tof2(uint32_t u) {
    __half2 h = *reinterpret_cast<__half2*>(&u);
    return __half22float2(h);
}
__device__ __forceinline__ void mma_f16(float c[4], const uint32_t a[4], const uint32_t b[2]) {
    asm volatile(
        "mma.sync.aligned.m16n8k16.row.col.f32.f16.f16.f32 "
        "{%0,%1,%2,%3}, {%4,%5,%6,%7}, {%8,%9}, {%0,%1,%2,%3};"
        : "+f"(c[0]), "+f"(c[1]), "+f"(c[2]), "+f"(c[3])
        : "r"(a[0]), "r"(a[1]), "r"(a[2]), "r"(a[3]), "r"(b[0]), "r"(b[1]));
}

// ---------------------------------------------------------------------------
// Prep: y16 = fp16(x @ Win) (blocks 0..767); B-fragment packing (768..799)
// ---------------------------------------------------------------------------
__global__ void __launch_bounds__(128)
prep_kernel(const float* __restrict__ x, const float* __restrict__ Win,
            const float* __restrict__ W1, const float* __restrict__ W2)
{
    const int bid = blockIdx.x, t = threadIdx.x;
    if (bid < ATOMS_) {
        __shared__ float xs[NB_];
        __shared__ float ys[NF_];
        xs[t] = x[bid*NB_ + t];
        __syncthreads();
        float acc = 0.f;
        #pragma unroll 16
        for (int gg = 0; gg < NB_; ++gg)
            acc = fmaf(xs[gg], Win[gg*NF_ + t], acc);
        ys[t] = acc;
        __syncthreads();
        if (t < 64)
            g_y16[bid*64 + t] = packh2(ys[2*t], ys[2*t + 1]);
    } else {
        int e = (bid - ATOMS_)*128 + t;          // 0..4095
        const float* W   = (e < 2048) ? W1 : W2;
        const int   kmax = (e < 2048) ? NANG_ : 128;
        uint32_t*   dst  = (e < 2048) ? g_W1p : g_W2p;
        int e2 = e & 2047;
        int lane = e2 & 31, ntp = (e2>>5)&1, p = (e2>>6)&7, ng = e2>>9;
        int g = lane>>2, c = lane&3;
        int n0 = ng*32 + ntp*16 + g;
        int n1 = n0 + 8;
        int k0 = 16*p + 2*c;
        auto rd = [&](int k, int n) -> float {
            return (k < kmax) ? W[k*128 + n] : 0.f;
        };
        uint4 v;
        v.x = packh2(rd(k0,   n0), rd(k0+1, n0));
        v.y = packh2(rd(k0+8, n0), rd(k0+9, n0));
        v.z = packh2(rd(k0,   n1), rd(k0+1, n1));
        v.w = packh2(rd(k0+8, n1), rd(k0+9, n1));
        reinterpret_cast<uint4*>(dst)[e2] = v;
    }
}

// ---------------------------------------------------------------------------
// Fused main kernel: depth-4 pipeline, ONE barrier per phase, 2 CTAs/SM
// phase ph: scatter(ph) || GEMM1(ph-1) || GEMM2(ph-2) || EW(ph-3)
// ---------------------------------------------------------------------------
__global__ void __launch_bounds__(256, 2)
fused_kernel(const float* __restrict__ triple,
             const int*   __restrict__ nj, const int* __restrict__ nk,
             const float* __restrict__ mask,
             const float* __restrict__ b1, const float* __restrict__ b2,
             const float* __restrict__ Wf2, const float* __restrict__ bf2,
             const float* __restrict__ Wd,  const float* __restrict__ bd,
             const float* __restrict__ x,   float* __restrict__ out)
{
    extern __shared__ uint32_t sm[];
    uint32_t* Tb[2] = { sm + SM_T0, sm + SM_T1 };
    uint32_t* Hb[2] = { sm + SM_H0, sm + SM_H1 };
    uint32_t* Wb[2] = { sm + SM_W0, sm + SM_W1 };
    float*    ex  = reinterpret_cast<float*>(sm + SM_EX);
    float* b1s = ex;
    float* b2s = ex + 128;
    int*   js4 = reinterpret_cast<int*>(ex + 256);   // [4][64]
    int*   ks4 = reinterpret_cast<int*>(ex + 512);   // [4][64]
    float* ms4 = ex + 768;                           // [4][64]
    // post-loop scratch aliases tile buffers (loop done by then)
    float* aggp = reinterpret_cast<float*>(sm);      // 1024
    float* aggs = aggp + 1024;                       // 128
    float* t1s  = aggs + 128;                        // 128

    const int t    = threadIdx.x;
    const int atom = blockIdx.x;
    const int bidx = atom / AT_;
    const int lane = t & 31;
    const int warp = t >> 5;
    const int g  = lane >> 2;
    const int c  = lane & 3;
    const int mg = warp >> 2;      // 0..1
    const int ng = warp & 3;       // 0..3

    if (t < 128) { b1s[t] = b1[t]; b2s[t] = b2[t]; }

    const int nb = atom * NBR_;
    const uint32_t* yb16 = g_y16 + bidx * AT_ * 64;
    const uint4* W1p4 = reinterpret_cast<const uint4*>(g_W1p);
    const uint4* W2p4 = reinterpret_cast<const uint4*>(g_W2p);

    const int cg = t & 31;
    const int rq = t >> 5;
    float4 acc4 = make_float4(0.f, 0.f, 0.f, 0.f);

    #pragma unroll 1
    for (int ph = 0; ph < NCHUNK_ + 3; ++ph) {

        // ---- stage S: scatter chunk ph into T[ph&1] ----
        if (ph < NCHUNK_) {
            uint32_t* Tdst = Tb[ph & 1];
            const int slot = ph & 3;
            const float* tbase = triple + ((size_t)nb + (size_t)ph*CHUNK_ + warp*8)*NANG_;
            #pragma unroll
            for (int i = 0; i < 8; ++i) {
                const float* trow = tbase + i*NANG_;
                uint32_t* srow = &Tdst[(warp*8 + i)*PH_];
                #pragma unroll
                for (int q = 0; q < 2; ++q) {
                    int k0 = 2*lane + 64*q;
                    float v0 = (k0     < NANG_) ? __ldg(trow + k0)     : 0.f;
                    float v1 = (k0 + 1 < NANG_) ? __ldg(trow + k0 + 1) : 0.f;
                    srow[lane + 32*q] = packh2(v0, v1);
                }
            }
            if (t < CHUNK_) {
                js4[slot*64 + t] = nj[nb + ph*CHUNK_ + t];
                ks4[slot*64 + t] = nk[nb + ph*CHUNK_ + t];
                ms4[slot*64 + t] = mask[nb + ph*CHUNK_ + t];
            }
        }

        // ---- stage G1: GEMM1 chunk c1 = ph-1 : H[c1&1] = ssp(T@W1+b1) ----
        if (ph >= 1 && ph <= NCHUNK_) {
            const int c1 = ph - 1;
            const uint32_t* Tc = Tb[c1 & 1];
            uint32_t*       Hc = Hb[c1 & 1];
            float acc[2][4][4];
            #pragma unroll
            for (int mt=0;mt<2;mt++)
                #pragma unroll
                for (int nt=0;nt<4;nt++)
                    #pragma unroll
                    for (int i=0;i<4;i++) acc[mt][nt][i]=0.f;
            #pragma unroll
            for (int p = 0; p < 8; ++p) {
                uint32_t a[2][4];
                #pragma unroll
                for (int mt = 0; mt < 2; ++mt) {
                    int r0 = (mg*32 + mt*16 + g)*PH_ + p*8;
                    a[mt][0]=Tc[r0          + c    ];
                    a[mt][1]=Tc[r0 + 8*PH_  + c    ];
                    a[mt][2]=Tc[r0          + c + 4];
                    a[mt][3]=Tc[r0 + 8*PH_  + c + 4];
                }
                #pragma unroll
                for (int ntp = 0; ntp < 2; ++ntp) {
                    uint4 B4 = __ldg(&W1p4[((ng*8 + p)*2 + ntp)*32 + lane]);
                    uint32_t bb0[2] = {B4.x, B4.y};
                    uint32_t bb1[2] = {B4.z, B4.w};
                    #pragma unroll
                    for (int mt = 0; mt < 2; ++mt) {
                        mma_f16(acc[mt][ntp*2    ], a[mt], bb0);
                        mma_f16(acc[mt][ntp*2 + 1], a[mt], bb1);
                    }
                }
            }
            #pragma unroll
            for (int mt = 0; mt < 2; ++mt)
                #pragma unroll
                for (int nt = 0; nt < 4; ++nt) {
                    int col0 = ng*32 + nt*8 + 2*c;
                    int w0   = ng*16 + nt*4 + c;
                    int rA = mg*32 + mt*16 + g;
                    Hc[rA*PH_ + w0] =
                        packh2(sspf(acc[mt][nt][0] + b1s[col0]),
                               sspf(acc[mt][nt][1] + b1s[col0+1]));
                    Hc[(rA+8)*PH_ + w0] =
                        packh2(sspf(acc[mt][nt][2] + b1s[col0]),
                               sspf(acc[mt][nt][3] + b1s[col0+1]));
                }
        }

        // ---- stage G2: GEMM2 chunk c2 = ph-2 : W[c2&1] = (H@W2+b2)*m ----
        if (ph >= 2 && ph <= NCHUNK_ + 1) {
            const int c2 = ph - 2;
            const int slot2 = c2 & 3;
            const uint32_t* Hc = Hb[c2 & 1];
            uint32_t*       Wc = Wb[c2 & 1];
            float acc[2][4][4];
            #pragma unroll
            for (int mt=0;mt<2;mt++)
                #pragma unroll
                for (int nt=0;nt<4;nt++)
                    #pragma unroll
                    for (int i=0;i<4;i++) acc[mt][nt][i]=0.f;
            #pragma unroll
            for (int p = 0; p < 8; ++p) {
                uint32_t a[2][4];
                #pragma unroll
                for (int mt = 0; mt < 2; ++mt) {
                    int r0 = (mg*32 + mt*16 + g)*PH_ + p*8;
                    a[mt][0]=Hc[r0          + c    ];
                    a[mt][1]=Hc[r0 + 8*PH_  + c    ];
                    a[mt][2]=Hc[r0          + c + 4];
                    a[mt][3]=Hc[r0 + 8*PH_  + c + 4];
                }
                #pragma unroll
                for (int ntp = 0; ntp < 2; ++ntp) {
                    uint4 B4 = __ldg(&W2p4[((ng*8 + p)*2 + ntp)*32 + lane]);
                    uint32_t bb0[2] = {B4.x, B4.y};
                    uint32_t bb1[2] = {B4.z, B4.w};
                    #pragma unroll
                    for (int mt = 0; mt < 2; ++mt) {
                        mma_f16(acc[mt][ntp*2    ], a[mt], bb0);
                        mma_f16(acc[mt][ntp*2 + 1], a[mt], bb1);
                    }
                }
            }
            #pragma unroll
            for (int mt = 0; mt < 2; ++mt) {
                int rA = mg*32 + mt*16 + g;
                float mA = ms4[slot2*64 + rA];
                float mB = ms4[slot2*64 + rA + 8];
                #pragma unroll
                for (int nt = 0; nt < 4; ++nt) {
                    int col0 = ng*32 + nt*8 + 2*c;
                    int w0   = ng*16 + nt*4 + c;
                    Wc[rA*PH_ + w0] =
                        packh2((acc[mt][nt][0] + b2s[col0])  * mA,
                               (acc[mt][nt][1] + b2s[col0+1])* mA);
                    Wc[(rA+8)*PH_ + w0] =
                        packh2((acc[mt][nt][2] + b2s[col0])  * mB,
                               (acc[mt][nt][3] + b2s[col0+1])* mB);
                }
            }
        }

        // ---- stage E: elementwise chunk c3 = ph-3 ----
        if (ph >= 3) {
            const int c3 = ph - 3;
            const int slot3 = c3 & 3;
            const uint32_t* Wc = Wb[c3 & 1];
            #pragma unroll
            for (int i = 0; i < 8; ++i) {
                int r = rq*8 + i;
                int jrow = js4[slot3*64 + r], krow = ks4[slot3*64 + r];
                uint2 jw = __ldg(reinterpret_cast<const uint2*>(yb16 + jrow*64 + cg*2));
                uint2 kw = __ldg(reinterpret_cast<const uint2*>(yb16 + krow*64 + cg*2));
                float2 j0 = h2tof2(jw.x), j1 = h2tof2(jw.y);
                float2 k0 = h2tof2(kw.x), k1 = h2tof2(kw.y);
                uint2 ww = *reinterpret_cast<const uint2*>(&Wc[r*PH_ + cg*2]);
                float2 wa = h2tof2(ww.x), wb = h2tof2(ww.y);
                acc4.x = fmaf(j0.x * k0.x, wa.x, acc4.x);
                acc4.y = fmaf(j0.y * k0.y, wa.y, acc4.y);
                acc4.z = fmaf(j1.x * k1.x, wb.x, acc4.z);
                acc4.w = fmaf(j1.y * k1.y, wb.y, acc4.w);
            }
        }

        __syncthreads();   // one barrier per phase
    }

    // ===== reduce acc4 across rq groups, then per-atom epilogue =====
    *reinterpret_cast<float4*>(&aggp[(rq*32 + cg)*4]) = acc4;
    __syncthreads();
    if (t < 128) {
        float s = 0.f;
        #pragma unroll
        for (int r = 0; r < 8; ++r) s += aggp[r*128 + t];
        aggs[t] = s;
    }
    __syncthreads();
    if (t < 128) {
        float a1 = bf2[t];
        #pragma unroll 8
        for (int gg = 0; gg < 128; ++gg)
            a1 = fmaf(aggs[gg], Wf2[gg*NB_ + t], a1);
        t1s[t] = sspf(a1);
    }
    __syncthreads();
    if (t < 128) {
        float a2 = bd[t];
        #pragma unroll 8
        for (int gg = 0; gg < 128; ++gg)
            a2 = fmaf(t1s[gg], Wd[gg*NB_ + t], a2);
        out[atom*NB_ + t] = x[atom*NB_ + t] + a2;
    }
}

// ---------------------------------------------------------------------------
extern "C" void kernel_launch(void* const* d_in, const int* in_sizes, int n_in,
                              void* d_out, int out_size)
{
    const float* x      = (const float*)d_in[0];
    const float* triple = (const float*)d_in[1];
    const int*   nj     = (const int*)  d_in[2];
    const int*   nk     = (const int*)  d_in[3];
    const float* mask   = (const float*)d_in[4];
    const float* W1     = (const float*)d_in[5];
    const float* b1     = (const float*)d_in[6];
    const float* W2     = (const float*)d_in[7];
    const float* b2     = (const float*)d_in[8];
    const float* Win    = (const float*)d_in[9];
    const float* Wf2    = (const float*)d_in[10];
    const float* bf2    = (const float*)d_in[11];
    const float* Wd     = (const float*)d_in[12];
    const float* bd     = (const float*)d_in[13];
    float* out = (float*)d_out;

    cudaFuncSetAttribute(fused_kernel,
                         cudaFuncAttributeMaxDynamicSharedMemorySize, SMEM_BYTES);

    prep_kernel<<<ATOMS_ + 32, 128>>>(x, Win, W1, W2);
    fused_kernel<<<ATOMS_, 256, SMEM_BYTES>>>(triple, nj, nk, mask,
                                              b1, b2, Wf2, bf2, Wd, bd, x, out);
}

// round 16
// speedup vs baseline: 1.4289x; 1.4289x over previous
#include <cuda_runtime.h>
#include <cuda_fp16.h>
#include <cstdint>

#define B_      8
#define AT_     96
#define NBR_    512
#define NANG_   125
#define NF_     128
#define NB_     128
#define ATOMS_  (B_*AT_)      // 768
#define CHUNK_  64
#define NCHUNK_ (NBR_/CHUNK_) // 8
#define PH_     68            // half2-word pitch (%32==4 -> conflict-free)

// smem layout (u32 units)  (identical to R12 best)
#define SM_TA   0
#define SM_TB   4352
#define SM_H    8704
#define SM_EX   13056
#define SMEM_U32   (SM_EX + 640)
#define SMEM_BYTES (SMEM_U32*4)   // 54,784 B -> 3 CTAs/SM

// prep kernel dynamic smem: Wins[16384] + xs[1024] + ys[1024] floats
#define PREP_SMEM_BYTES ((16384 + 1024 + 1024) * 4)   // 73,728 B

__device__ __align__(16) uint32_t g_y16[ATOMS_ * 64];   // y as half2 words
// packed fp16 B fragments: uint4 idx = ((ng*8+p)*2+ntp)*32+lane
__device__ __align__(16) uint32_t g_W1p[2048*4];
__device__ __align__(16) uint32_t g_W2p[2048*4];

__device__ __forceinline__ float sspf(float x) {
    return fmaxf(x, 0.f) + __logf(1.f + __expf(-fabsf(x))) - 0.6931471805599453f;
}
__device__ __forceinline__ uint32_t packh2(float lo, float hi) {
    __half2 h = __halves2half2(__float2half_rn(lo), __float2half_rn(hi));
    return *reinterpret_cast<uint32_t*>(&h);
}
__device__ __forceinline__ float2 h2tof2(uint32_t u) {
    __half2 h = *reinterpret_cast<__half2*>(&u);
    return __half22float2(h);
}
__device__ __forceinline__ void mma_f16(float c[4], const uint32_t a[4], const uint32_t b[2]) {
    asm volatile(
        "mma.sync.aligned.m16n8k16.row.col.f32.f16.f16.f32 "
        "{%0,%1,%2,%3}, {%4,%5,%6,%7}, {%8,%9}, {%0,%1,%2,%3};"
        : "+f"(c[0]), "+f"(c[1]), "+f"(c[2]), "+f"(c[3])
        : "r"(a[0]), "r"(a[1]), "r"(a[2]), "r"(a[3]), "r"(b[0]), "r"(b[1]));
}

// ---------------------------------------------------------------------------
// Prep: blocks 0..95 -> y16 for 8 atoms each (Win staged in smem once);
//       blocks 96..127 -> fp16 B-fragment packing
// ---------------------------------------------------------------------------
__global__ void __launch_bounds__(256)
prep_kernel(const float* __restrict__ x, const float* __restrict__ Win,
            const float* __restrict__ W1, const float* __restrict__ W2)
{
    const int bid = blockIdx.x, t = threadIdx.x;
    if (bid < 96) {
        extern __shared__ float ps[];
        float* Wins = ps;               // 16384
        float* xs   = ps + 16384;       // 1024 (8 atoms x 128)
        float* ys   = ps + 17408;       // 1024

        const int atom0 = bid * 8;
        // stage Win (128x128 f32) via float4
        {
            const float4* src = reinterpret_cast<const float4*>(Win);
            float4* dst = reinterpret_cast<float4*>(Wins);
            #pragma unroll
            for (int i = 0; i < 16; ++i) dst[t + i*256] = src[t + i*256];
        }
        // stage x rows for 8 atoms
        {
            const float4* src = reinterpret_cast<const float4*>(x + atom0*NB_);
            float4* dst = reinterpret_cast<float4*>(xs);
            dst[t] = src[t];            // 256 float4 = 1024 floats
        }
        __syncthreads();

        // each thread: 4 atoms x 1 column
        const int sub = t >> 7;         // 0..1 -> atoms 4sub..4sub+3
        const int col = t & 127;
        float acc[4] = {0.f, 0.f, 0.f, 0.f};
        #pragma unroll 8
        for (int gg = 0; gg < NB_; ++gg) {
            float w = Wins[gg*NF_ + col];
            acc[0] = fmaf(xs[(sub*4    )*NB_ + gg], w, acc[0]);
            acc[1] = fmaf(xs[(sub*4 + 1)*NB_ + gg], w, acc[1]);
            acc[2] = fmaf(xs[(sub*4 + 2)*NB_ + gg], w, acc[2]);
            acc[3] = fmaf(xs[(sub*4 + 3)*NB_ + gg], w, acc[3]);
        }
        #pragma unroll
        for (int a = 0; a < 4; ++a)
            ys[(sub*4 + a)*NF_ + col] = acc[a];
        __syncthreads();

        // pack to fp16: 512 half2 words
        #pragma unroll
        for (int idx = t; idx < 512; idx += 256) {
            int al = idx >> 6, w = idx & 63;
            g_y16[(atom0 + al)*64 + w] = packh2(ys[al*NF_ + 2*w], ys[al*NF_ + 2*w + 1]);
        }
    } else {
        int e = (bid - 96)*128 + t;              // 0..4095
        const float* W   = (e < 2048) ? W1 : W2;
        const int   kmax = (e < 2048) ? NANG_ : 128;
        uint32_t*   dst  = (e < 2048) ? g_W1p : g_W2p;
        int e2 = e & 2047;
        int lane = e2 & 31, ntp = (e2>>5)&1, p = (e2>>6)&7, ng = e2>>9;
        int g = lane>>2, c = lane&3;
        int n0 = ng*32 + ntp*16 + g;
        int n1 = n0 + 8;
        int k0 = 16*p + 2*c;
        auto rd = [&](int k, int n) -> float {
            return (k < kmax) ? W[k*128 + n] : 0.f;
        };
        uint4 v;
        v.x = packh2(rd(k0,   n0), rd(k0+1, n0));
        v.y = packh2(rd(k0+8, n0), rd(k0+9, n0));
        v.z = packh2(rd(k0,   n1), rd(k0+1, n1));
        v.w = packh2(rd(k0+8, n1), rd(k0+9, n1));
        reinterpret_cast<uint4*>(dst)[e2] = v;
    }
}

// ---------------------------------------------------------------------------
// Fused main kernel: pipelined, 2 barriers/chunk, 3 CTAs/SM (R12, verbatim)
// ---------------------------------------------------------------------------
__global__ void __launch_bounds__(256, 3)
fused_kernel(const float* __restrict__ triple,
             const int*   __restrict__ nj, const int* __restrict__ nk,
             const float* __restrict__ mask,
             const float* __restrict__ b1, const float* __restrict__ b2,
             const float* __restrict__ Wf2, const float* __restrict__ bf2,
             const float* __restrict__ Wd,  const float* __restrict__ bd,
             const float* __restrict__ x,   float* __restrict__ out)
{
    extern __shared__ uint32_t sm[];
    uint32_t* TA  = sm + SM_TA;
    uint32_t* TB  = sm + SM_TB;
    uint32_t* H16 = sm + SM_H;
    float*    ex  = reinterpret_cast<float*>(sm + SM_EX);
    float* b1s = ex;
    float* b2s = ex + 128;
    int*   js2 = reinterpret_cast<int*>(ex + 256);   // [2][64]
    int*   ks2 = reinterpret_cast<int*>(ex + 384);   // [2][64]
    float* ms2 = ex + 512;                           // [2][64]
    float* aggp = reinterpret_cast<float*>(sm);      // post-loop (aliases TA)
    float* aggs = aggp + 1024;
    float* t1s  = aggs + 128;

    const int t    = threadIdx.x;
    const int atom = blockIdx.x;
    const int bidx = atom / AT_;
    const int lane = t & 31;
    const int warp = t >> 5;
    const int g  = lane >> 2;
    const int c  = lane & 3;
    const int mg = warp >> 2;      // 0..1
    const int ng = warp & 3;       // 0..3

    if (t < 128) { b1s[t] = b1[t]; b2s[t] = b2[t]; }

    const int nb = atom * NBR_;
    const uint32_t* yb16 = g_y16 + bidx * AT_ * 64;
    const uint4* W1p4 = reinterpret_cast<const uint4*>(g_W1p);
    const uint4* W2p4 = reinterpret_cast<const uint4*>(g_W2p);

    const int cg = t & 31;
    const int rq = t >> 5;
    float4 acc4 = make_float4(0.f, 0.f, 0.f, 0.f);

    auto scatter = [&](int ch, uint32_t* Tb, int buf) {
        const float* tbase = triple + ((size_t)nb + (size_t)ch*CHUNK_ + warp*8)*NANG_;
        #pragma unroll
        for (int i = 0; i < 8; ++i) {
            const float* trow = tbase + i*NANG_;
            uint32_t* srow = &Tb[(warp*8 + i)*PH_];
            #pragma unroll
            for (int q = 0; q < 2; ++q) {
                int k0 = 2*lane + 64*q;
                float v0 = (k0     < NANG_) ? __ldg(trow + k0)     : 0.f;
                float v1 = (k0 + 1 < NANG_) ? __ldg(trow + k0 + 1) : 0.f;
                srow[lane + 32*q] = packh2(v0, v1);
            }
        }
        if (t < CHUNK_) {
            js2[buf*64 + t] = nj[nb + ch*CHUNK_ + t];
            ks2[buf*64 + t] = nk[nb + ch*CHUNK_ + t];
            ms2[buf*64 + t] = mask[nb + ch*CHUNK_ + t];
        }
    };

    scatter(0, TA, 0);
    __syncthreads();

    for (int ch = 0; ch < NCHUNK_; ++ch) {
        const int cur = ch & 1;
        uint32_t* Tc  = cur ? TB : TA;
        uint32_t* Tn  = cur ? TA : TB;
        uint32_t* W16 = Tc;            // W_triple output aliases dead T buffer

        // ================= GEMM1: H = ssp(T @ W1 + b1) =================
        {
            float acc[2][4][4];
            #pragma unroll
            for (int mt=0;mt<2;mt++)
                #pragma unroll
                for (int nt=0;nt<4;nt++)
                    #pragma unroll
                    for (int i=0;i<4;i++) acc[mt][nt][i]=0.f;
            #pragma unroll
            for (int p = 0; p < 8; ++p) {
                uint32_t a[2][4];
                #pragma unroll
                for (int mt = 0; mt < 2; ++mt) {
                    int r0 = (mg*32 + mt*16 + g)*PH_ + p*8;
                    a[mt][0]=Tc[r0          + c    ];
                    a[mt][1]=Tc[r0 + 8*PH_  + c    ];
                    a[mt][2]=Tc[r0          + c + 4];
                    a[mt][3]=Tc[r0 + 8*PH_  + c + 4];
                }
                #pragma unroll
                for (int ntp = 0; ntp < 2; ++ntp) {
                    uint4 B4 = __ldg(&W1p4[((ng*8 + p)*2 + ntp)*32 + lane]);
                    uint32_t bb0[2] = {B4.x, B4.y};
                    uint32_t bb1[2] = {B4.z, B4.w};
                    #pragma unroll
                    for (int mt = 0; mt < 2; ++mt) {
                        mma_f16(acc[mt][ntp*2    ], a[mt], bb0);
                        mma_f16(acc[mt][ntp*2 + 1], a[mt], bb1);
                    }
                }
            }
            #pragma unroll
            for (int mt = 0; mt < 2; ++mt)
                #pragma unroll
                for (int nt = 0; nt < 4; ++nt) {
                    int col0 = ng*32 + nt*8 + 2*c;
                    int w0   = ng*16 + nt*4 + c;
                    int rA = mg*32 + mt*16 + g;
                    H16[rA*PH_ + w0] =
                        packh2(sspf(acc[mt][nt][0] + b1s[col0]),
                               sspf(acc[mt][nt][1] + b1s[col0+1]));
                    H16[(rA+8)*PH_ + w0] =
                        packh2(sspf(acc[mt][nt][2] + b1s[col0]),
                               sspf(acc[mt][nt][3] + b1s[col0+1]));
                }
        }
        __syncthreads();   // H ready; Tc reads done (Tc now reusable as W16)

        // ---- pipelined scatter of next chunk (overlaps GEMM2 issue) ----
        if (ch + 1 < NCHUNK_)
            scatter(ch + 1, Tn, cur ^ 1);

        // ================= GEMM2: W16 = (H @ W2 + b2) * m  [fp16 out] =================
        {
            float acc[2][4][4];
            #pragma unroll
            for (int mt=0;mt<2;mt++)
                #pragma unroll
                for (int nt=0;nt<4;nt++)
                    #pragma unroll
                    for (int i=0;i<4;i++) acc[mt][nt][i]=0.f;
            #pragma unroll
            for (int p = 0; p < 8; ++p) {
                uint32_t a[2][4];
                #pragma unroll
                for (int mt = 0; mt < 2; ++mt) {
                    int r0 = (mg*32 + mt*16 + g)*PH_ + p*8;
                    a[mt][0]=H16[r0          + c    ];
                    a[mt][1]=H16[r0 + 8*PH_  + c    ];
                    a[mt][2]=H16[r0          + c + 4];
                    a[mt][3]=H16[r0 + 8*PH_  + c + 4];
                }
                #pragma unroll
                for (int ntp = 0; ntp < 2; ++ntp) {
                    uint4 B4 = __ldg(&W2p4[((ng*8 + p)*2 + ntp)*32 + lane]);
                    uint32_t bb0[2] = {B4.x, B4.y};
                    uint32_t bb1[2] = {B4.z, B4.w};
                    #pragma unroll
                    for (int mt = 0; mt < 2; ++mt) {
                        mma_f16(acc[mt][ntp*2    ], a[mt], bb0);
                        mma_f16(acc[mt][ntp*2 + 1], a[mt], bb1);
                    }
                }
            }
            #pragma unroll
            for (int mt = 0; mt < 2; ++mt) {
                int rA = mg*32 + mt*16 + g;
                float mA = ms2[cur*64 + rA];
                float mB = ms2[cur*64 + rA + 8];
                #pragma unroll
                for (int nt = 0; nt < 4; ++nt) {
                    int col0 = ng*32 + nt*8 + 2*c;
                    int w0   = ng*16 + nt*4 + c;
                    W16[rA*PH_ + w0] =
                        packh2((acc[mt][nt][0] + b2s[col0])  * mA,
                               (acc[mt][nt][1] + b2s[col0+1])* mA);
                    W16[(rA+8)*PH_ + w0] =
                        packh2((acc[mt][nt][2] + b2s[col0])  * mB,
                               (acc[mt][nt][3] + b2s[col0+1])* mB);
                }
            }
        }
        __syncthreads();   // W16 ready; Tn writes complete

        // ===== elementwise: acc4 += yj4*yk4*wt4 (y fp16, mask folded in wt) =====
        #pragma unroll
        for (int i = 0; i < 8; ++i) {
            int r = rq*8 + i;
            int jrow = js2[cur*64 + r], krow = ks2[cur*64 + r];
            uint2 jw = __ldg(reinterpret_cast<const uint2*>(yb16 + jrow*64 + cg*2));
            uint2 kw = __ldg(reinterpret_cast<const uint2*>(yb16 + krow*64 + cg*2));
            float2 j0 = h2tof2(jw.x), j1 = h2tof2(jw.y);
            float2 k0 = h2tof2(kw.x), k1 = h2tof2(kw.y);
            uint2 ww = *reinterpret_cast<const uint2*>(&W16[r*PH_ + cg*2]);
            float2 wa = h2tof2(ww.x), wb = h2tof2(ww.y);
            acc4.x = fmaf(j0.x * k0.x, wa.x, acc4.x);
            acc4.y = fmaf(j0.y * k0.y, wa.y, acc4.y);
            acc4.z = fmaf(j1.x * k1.x, wb.x, acc4.z);
            acc4.w = fmaf(j1.y * k1.y, wb.y, acc4.w);
        }
    }

    // ===== reduce acc4 across rq groups, then per-atom epilogue =====
    __syncthreads();
    *reinterpret_cast<float4*>(&aggp[(rq*32 + cg)*4]) = acc4;
    __syncthreads();
    if (t < 128) {
        float s = 0.f;
        #pragma unroll
        for (int r = 0; r < 8; ++r) s += aggp[r*128 + t];
        aggs[t] = s;
    }
    __syncthreads();
    if (t < 128) {
        float a1 = bf2[t];
        #pragma unroll 8
        for (int gg = 0; gg < 128; ++gg)
            a1 = fmaf(aggs[gg], Wf2[gg*NB_ + t], a1);
        t1s[t] = sspf(a1);
    }
    __syncthreads();
    if (t < 128) {
        float a2 = bd[t];
        #pragma unroll 8
        for (int gg = 0; gg < 128; ++gg)
            a2 = fmaf(t1s[gg], Wd[gg*NB_ + t], a2);
        out[atom*NB_ + t] = x[atom*NB_ + t] + a2;
    }
}

// ---------------------------------------------------------------------------
extern "C" void kernel_launch(void* const* d_in, const int* in_sizes, int n_in,
                              void* d_out, int out_size)
{
    const float* x      = (const float*)d_in[0];
    const float* triple = (const float*)d_in[1];
    const int*   nj     = (const int*)  d_in[2];
    const int*   nk     = (const int*)  d_in[3];
    const float* mask   = (const float*)d_in[4];
    const float* W1     = (const float*)d_in[5];
    const float* b1     = (const float*)d_in[6];
    const float* W2     = (const float*)d_in[7];
    const float* b2     = (const float*)d_in[8];
    const float* Win    = (const float*)d_in[9];
    const float* Wf2    = (const float*)d_in[10];
    const float* bf2    = (const float*)d_in[11];
    const float* Wd     = (const float*)d_in[12];
    const float* bd     = (const float*)d_in[13];
    float* out = (float*)d_out;

    cudaFuncSetAttribute(prep_kernel,
                         cudaFuncAttributeMaxDynamicSharedMemorySize, PREP_SMEM_BYTES);
    cudaFuncSetAttribute(fused_kernel,
                         cudaFuncAttributeMaxDynamicSharedMemorySize, SMEM_BYTES);

    prep_kernel<<<128, 256, PREP_SMEM_BYTES>>>(x, Win, W1, W2);
    fused_kernel<<<ATOMS_, 256, SMEM_BYTES>>>(triple, nj, nk, mask,
                                              b1, b2, Wf2, bf2, Wd, bd, x, out);
}

// round 17
// speedup vs baseline: 1.4760x; 1.0330x over previous
#include <cuda_runtime.h>
#include <cuda_fp16.h>
#include <cstdint>

#define B_      8
#define AT_     96
#define NBR_    512
#define NANG_   125
#define NF_     128
#define NB_     128
#define ATOMS_  (B_*AT_)      // 768
#define CHUNK_  64
#define NCHUNK_ (NBR_/CHUNK_) // 8
#define PH_     68            // half2-word pitch (%32==4 -> conflict-free)

// smem layout (u32 units)  (identical to R16 best)
#define SM_TA   0
#define SM_TB   4352
#define SM_H    8704
#define SM_EX   13056
#define SMEM_U32   (SM_EX + 640)
#define SMEM_BYTES (SMEM_U32*4)   // 54,784 B -> 3 CTAs/SM

// prep kernel dynamic smem: Wins[16384] + xs[1024] + ys[1024] floats
#define PREP_SMEM_BYTES ((16384 + 1024 + 1024) * 4)   // 73,728 B

__device__ __align__(16) uint32_t g_y16[ATOMS_ * 64];   // y as half2 words
// packed fp16 B fragments: uint4 idx = ((ng*8+p)*2+ntp)*32+lane
__device__ __align__(16) uint32_t g_W1p[2048*4];
__device__ __align__(16) uint32_t g_W2p[2048*4];

__device__ __forceinline__ float sspf(float x) {
    return fmaxf(x, 0.f) + __logf(1.f + __expf(-fabsf(x))) - 0.6931471805599453f;
}
__device__ __forceinline__ uint32_t packh2(float lo, float hi) {
    __half2 h = __halves2half2(__float2half_rn(lo), __float2half_rn(hi));
    return *reinterpret_cast<uint32_t*>(&h);
}
__device__ __forceinline__ float2 h2tof2(uint32_t u) {
    __half2 h = *reinterpret_cast<__half2*>(&u);
    return __half22float2(h);
}
__device__ __forceinline__ void mma_f16(float c[4], const uint32_t a[4], const uint32_t b[2]) {
    asm volatile(
        "mma.sync.aligned.m16n8k16.row.col.f32.f16.f16.f32 "
        "{%0,%1,%2,%3}, {%4,%5,%6,%7}, {%8,%9}, {%0,%1,%2,%3};"
        : "+f"(c[0]), "+f"(c[1]), "+f"(c[2]), "+f"(c[3])
        : "r"(a[0]), "r"(a[1]), "r"(a[2]), "r"(a[3]), "r"(b[0]), "r"(b[1]));
}

// ---------------------------------------------------------------------------
// Prep: blocks 0..95 -> y16 for 8 atoms each (Win staged in smem once);
//       blocks 96..127 -> fp16 B-fragment packing
// ---------------------------------------------------------------------------
__global__ void __launch_bounds__(256)
prep_kernel(const float* __restrict__ x, const float* __restrict__ Win,
            const float* __restrict__ W1, const float* __restrict__ W2)
{
    const int bid = blockIdx.x, t = threadIdx.x;
    if (bid < 96) {
        extern __shared__ float ps[];
        float* Wins = ps;               // 16384
        float* xs   = ps + 16384;       // 1024 (8 atoms x 128)
        float* ys   = ps + 17408;       // 1024

        const int atom0 = bid * 8;
        {
            const float4* src = reinterpret_cast<const float4*>(Win);
            float4* dst = reinterpret_cast<float4*>(Wins);
            #pragma unroll
            for (int i = 0; i < 16; ++i) dst[t + i*256] = src[t + i*256];
        }
        {
            const float4* src = reinterpret_cast<const float4*>(x + atom0*NB_);
            float4* dst = reinterpret_cast<float4*>(xs);
            dst[t] = src[t];
        }
        __syncthreads();

        const int sub = t >> 7;
        const int col = t & 127;
        float acc[4] = {0.f, 0.f, 0.f, 0.f};
        #pragma unroll 8
        for (int gg = 0; gg < NB_; ++gg) {
            float w = Wins[gg*NF_ + col];
            acc[0] = fmaf(xs[(sub*4    )*NB_ + gg], w, acc[0]);
            acc[1] = fmaf(xs[(sub*4 + 1)*NB_ + gg], w, acc[1]);
            acc[2] = fmaf(xs[(sub*4 + 2)*NB_ + gg], w, acc[2]);
            acc[3] = fmaf(xs[(sub*4 + 3)*NB_ + gg], w, acc[3]);
        }
        #pragma unroll
        for (int a = 0; a < 4; ++a)
            ys[(sub*4 + a)*NF_ + col] = acc[a];
        __syncthreads();

        #pragma unroll
        for (int idx = t; idx < 512; idx += 256) {
            int al = idx >> 6, w = idx & 63;
            g_y16[(atom0 + al)*64 + w] = packh2(ys[al*NF_ + 2*w], ys[al*NF_ + 2*w + 1]);
        }
    } else {
        int e = (bid - 96)*128 + t;              // 0..4095
        const float* W   = (e < 2048) ? W1 : W2;
        const int   kmax = (e < 2048) ? NANG_ : 128;
        uint32_t*   dst  = (e < 2048) ? g_W1p : g_W2p;
        int e2 = e & 2047;
        int lane = e2 & 31, ntp = (e2>>5)&1, p = (e2>>6)&7, ng = e2>>9;
        int g = lane>>2, c = lane&3;
        int n0 = ng*32 + ntp*16 + g;
        int n1 = n0 + 8;
        int k0 = 16*p + 2*c;
        auto rd = [&](int k, int n) -> float {
            return (k < kmax) ? W[k*128 + n] : 0.f;
        };
        uint4 v;
        v.x = packh2(rd(k0,   n0), rd(k0+1, n0));
        v.y = packh2(rd(k0+8, n0), rd(k0+9, n0));
        v.z = packh2(rd(k0,   n1), rd(k0+1, n1));
        v.w = packh2(rd(k0+8, n1), rd(k0+9, n1));
        reinterpret_cast<uint4*>(dst)[e2] = v;
    }
}

// ---------------------------------------------------------------------------
// Fused main kernel: pipelined, 2 barriers/chunk, 3 CTAs/SM
// Single-use streams (triple/nj/nk/mask) use __ldcs to preserve L1 for B + y16
// ---------------------------------------------------------------------------
__global__ void __launch_bounds__(256, 3)
fused_kernel(const float* __restrict__ triple,
             const int*   __restrict__ nj, const int* __restrict__ nk,
             const float* __restrict__ mask,
             const float* __restrict__ b1, const float* __restrict__ b2,
             const float* __restrict__ Wf2, const float* __restrict__ bf2,
             const float* __restrict__ Wd,  const float* __restrict__ bd,
             const float* __restrict__ x,   float* __restrict__ out)
{
    extern __shared__ uint32_t sm[];
    uint32_t* TA  = sm + SM_TA;
    uint32_t* TB  = sm + SM_TB;
    uint32_t* H16 = sm + SM_H;
    float*    ex  = reinterpret_cast<float*>(sm + SM_EX);
    float* b1s = ex;
    float* b2s = ex + 128;
    int*   js2 = reinterpret_cast<int*>(ex + 256);   // [2][64]
    int*   ks2 = reinterpret_cast<int*>(ex + 384);   // [2][64]
    float* ms2 = ex + 512;                           // [2][64]
    float* aggp = reinterpret_cast<float*>(sm);      // post-loop (aliases TA)
    float* aggs = aggp + 1024;
    float* t1s  = aggs + 128;

    const int t    = threadIdx.x;
    const int atom = blockIdx.x;
    const int bidx = atom / AT_;
    const int lane = t & 31;
    const int warp = t >> 5;
    const int g  = lane >> 2;
    const int c  = lane & 3;
    const int mg = warp >> 2;      // 0..1
    const int ng = warp & 3;       // 0..3

    if (t < 128) { b1s[t] = b1[t]; b2s[t] = b2[t]; }

    const int nb = atom * NBR_;
    const uint32_t* yb16 = g_y16 + bidx * AT_ * 64;
    const uint4* W1p4 = reinterpret_cast<const uint4*>(g_W1p);
    const uint4* W2p4 = reinterpret_cast<const uint4*>(g_W2p);

    const int cg = t & 31;
    const int rq = t >> 5;
    float4 acc4 = make_float4(0.f, 0.f, 0.f, 0.f);

    auto scatter = [&](int ch, uint32_t* Tb, int buf) {
        const float* tbase = triple + ((size_t)nb + (size_t)ch*CHUNK_ + warp*8)*NANG_;
        #pragma unroll
        for (int i = 0; i < 8; ++i) {
            const float* trow = tbase + i*NANG_;
            uint32_t* srow = &Tb[(warp*8 + i)*PH_];
            #pragma unroll
            for (int q = 0; q < 2; ++q) {
                int k0 = 2*lane + 64*q;
                float v0 = (k0     < NANG_) ? __ldcs(trow + k0)     : 0.f;
                float v1 = (k0 + 1 < NANG_) ? __ldcs(trow + k0 + 1) : 0.f;
                srow[lane + 32*q] = packh2(v0, v1);
            }
        }
        if (t < CHUNK_) {
            js2[buf*64 + t] = __ldcs(nj + nb + ch*CHUNK_ + t);
            ks2[buf*64 + t] = __ldcs(nk + nb + ch*CHUNK_ + t);
            ms2[buf*64 + t] = __ldcs(mask + nb + ch*CHUNK_ + t);
        }
    };

    scatter(0, TA, 0);
    __syncthreads();

    for (int ch = 0; ch < NCHUNK_; ++ch) {
        const int cur = ch & 1;
        uint32_t* Tc  = cur ? TB : TA;
        uint32_t* Tn  = cur ? TA : TB;
        uint32_t* W16 = Tc;            // W_triple output aliases dead T buffer

        // ================= GEMM1: H = ssp(T @ W1 + b1) =================
        {
            float acc[2][4][4];
            #pragma unroll
            for (int mt=0;mt<2;mt++)
                #pragma unroll
                for (int nt=0;nt<4;nt++)
                    #pragma unroll
                    for (int i=0;i<4;i++) acc[mt][nt][i]=0.f;
            #pragma unroll
            for (int p = 0; p < 8; ++p) {
                uint32_t a[2][4];
                #pragma unroll
                for (int mt = 0; mt < 2; ++mt) {
                    int r0 = (mg*32 + mt*16 + g)*PH_ + p*8;
                    a[mt][0]=Tc[r0          + c    ];
                    a[mt][1]=Tc[r0 + 8*PH_  + c    ];
                    a[mt][2]=Tc[r0          + c + 4];
                    a[mt][3]=Tc[r0 + 8*PH_  + c + 4];
                }
                #pragma unroll
                for (int ntp = 0; ntp < 2; ++ntp) {
                    uint4 B4 = __ldg(&W1p4[((ng*8 + p)*2 + ntp)*32 + lane]);
                    uint32_t bb0[2] = {B4.x, B4.y};
                    uint32_t bb1[2] = {B4.z, B4.w};
                    #pragma unroll
                    for (int mt = 0; mt < 2; ++mt) {
                        mma_f16(acc[mt][ntp*2    ], a[mt], bb0);
                        mma_f16(acc[mt][ntp*2 + 1], a[mt], bb1);
                    }
                }
            }
            #pragma unroll
            for (int mt = 0; mt < 2; ++mt)
                #pragma unroll
                for (int nt = 0; nt < 4; ++nt) {
                    int col0 = ng*32 + nt*8 + 2*c;
                    int w0   = ng*16 + nt*4 + c;
                    int rA = mg*32 + mt*16 + g;
                    H16[rA*PH_ + w0] =
                        packh2(sspf(acc[mt][nt][0] + b1s[col0]),
                               sspf(acc[mt][nt][1] + b1s[col0+1]));
                    H16[(rA+8)*PH_ + w0] =
                        packh2(sspf(acc[mt][nt][2] + b1s[col0]),
                               sspf(acc[mt][nt][3] + b1s[col0+1]));
                }
        }
        __syncthreads();   // H ready; Tc reads done (Tc now reusable as W16)

        // ---- pipelined scatter of next chunk (overlaps GEMM2 issue) ----
        if (ch + 1 < NCHUNK_)
            scatter(ch + 1, Tn, cur ^ 1);

        // ================= GEMM2: W16 = (H @ W2 + b2) * m  [fp16 out] =================
        {
            float acc[2][4][4];
            #pragma unroll
            for (int mt=0;mt<2;mt++)
                #pragma unroll
                for (int nt=0;nt<4;nt++)
                    #pragma unroll
                    for (int i=0;i<4;i++) acc[mt][nt][i]=0.f;
            #pragma unroll
            for (int p = 0; p < 8; ++p) {
                uint32_t a[2][4];
                #pragma unroll
                for (int mt = 0; mt < 2; ++mt) {
                    int r0 = (mg*32 + mt*16 + g)*PH_ + p*8;
                    a[mt][0]=H16[r0          + c    ];
                    a[mt][1]=H16[r0 + 8*PH_  + c    ];
                    a[mt][2]=H16[r0          + c + 4];
                    a[mt][3]=H16[r0 + 8*PH_  + c + 4];
                }
                #pragma unroll
                for (int ntp = 0; ntp < 2; ++ntp) {
                    uint4 B4 = __ldg(&W2p4[((ng*8 + p)*2 + ntp)*32 + lane]);
                    uint32_t bb0[2] = {B4.x, B4.y};
                    uint32_t bb1[2] = {B4.z, B4.w};
                    #pragma unroll
                    for (int mt = 0; mt < 2; ++mt) {
                        mma_f16(acc[mt][ntp*2    ], a[mt], bb0);
                        mma_f16(acc[mt][ntp*2 + 1], a[mt], bb1);
                    }
                }
            }
            #pragma unroll
            for (int mt = 0; mt < 2; ++mt) {
                int rA = mg*32 + mt*16 + g;
                float mA = ms2[cur*64 + rA];
                float mB = ms2[cur*64 + rA + 8];
                #pragma unroll
                for (int nt = 0; nt < 4; ++nt) {
                    int col0 = ng*32 + nt*8 + 2*c;
                    int w0   = ng*16 + nt*4 + c;
                    W16[rA*PH_ + w0] =
                        packh2((acc[mt][nt][0] + b2s[col0])  * mA,
                               (acc[mt][nt][1] + b2s[col0+1])* mA);
                    W16[(rA+8)*PH_ + w0] =
                        packh2((acc[mt][nt][2] + b2s[col0])  * mB,
                               (acc[mt][nt][3] + b2s[col0+1])* mB);
                }
            }
        }
        __syncthreads();   // W16 ready; Tn writes complete

        // ===== elementwise: acc4 += yj4*yk4*wt4 (y fp16, mask folded in wt) =====
        #pragma unroll
        for (int i = 0; i < 8; ++i) {
            int r = rq*8 + i;
            int jrow = js2[cur*64 + r], krow = ks2[cur*64 + r];
            uint2 jw = __ldg(reinterpret_cast<const uint2*>(yb16 + jrow*64 + cg*2));
            uint2 kw = __ldg(reinterpret_cast<const uint2*>(yb16 + krow*64 + cg*2));
            float2 j0 = h2tof2(jw.x), j1 = h2tof2(jw.y);
            float2 k0 = h2tof2(kw.x), k1 = h2tof2(kw.y);
            uint2 ww = *reinterpret_cast<const uint2*>(&W16[r*PH_ + cg*2]);
            float2 wa = h2tof2(ww.x), wb = h2tof2(ww.y);
            acc4.x = fmaf(j0.x * k0.x, wa.x, acc4.x);
            acc4.y = fmaf(j0.y * k0.y, wa.y, acc4.y);
            acc4.z = fmaf(j1.x * k1.x, wb.x, acc4.z);
            acc4.w = fmaf(j1.y * k1.y, wb.y, acc4.w);
        }
    }

    // ===== reduce acc4 across rq groups, then per-atom epilogue =====
    __syncthreads();
    *reinterpret_cast<float4*>(&aggp[(rq*32 + cg)*4]) = acc4;
    __syncthreads();
    if (t < 128) {
        float s = 0.f;
        #pragma unroll
        for (int r = 0; r < 8; ++r) s += aggp[r*128 + t];
        aggs[t] = s;
    }
    __syncthreads();
    if (t < 128) {
        float a1 = bf2[t];
        #pragma unroll 8
        for (int gg = 0; gg < 128; ++gg)
            a1 = fmaf(aggs[gg], Wf2[gg*NB_ + t], a1);
        t1s[t] = sspf(a1);
    }
    __syncthreads();
    if (t < 128) {
        float a2 = bd[t];
        #pragma unroll 8
        for (int gg = 0; gg < 128; ++gg)
            a2 = fmaf(t1s[gg], Wd[gg*NB_ + t], a2);
        out[atom*NB_ + t] = x[atom*NB_ + t] + a2;
    }
}

// ---------------------------------------------------------------------------
extern "C" void kernel_launch(void* const* d_in, const int* in_sizes, int n_in,
                              void* d_out, int out_size)
{
    const float* x      = (const float*)d_in[0];
    const float* triple = (const float*)d_in[1];
    const int*   nj     = (const int*)  d_in[2];
    const int*   nk     = (const int*)  d_in[3];
    const float* mask   = (const float*)d_in[4];
    const float* W1     = (const float*)d_in[5];
    const float* b1     = (const float*)d_in[6];
    const float* W2     = (const float*)d_in[7];
    const float* b2     = (const float*)d_in[8];
    const float* Win    = (const float*)d_in[9];
    const float* Wf2    = (const float*)d_in[10];
    const float* bf2    = (const float*)d_in[11];
    const float* Wd     = (const float*)d_in[12];
    const float* bd     = (const float*)d_in[13];
    float* out = (float*)d_out;

    cudaFuncSetAttribute(prep_kernel,
                         cudaFuncAttributeMaxDynamicSharedMemorySize, PREP_SMEM_BYTES);
    cudaFuncSetAttribute(fused_kernel,
                         cudaFuncAttributeMaxDynamicSharedMemorySize, SMEM_BYTES);

    prep_kernel<<<128, 256, PREP_SMEM_BYTES>>>(x, Win, W1, W2);
    fused_kernel<<<ATOMS_, 256, SMEM_BYTES>>>(triple, nj, nk, mask,
                                              b1, b2, Wf2, bf2, Wd, bd, x, out);
}